// round 11
// baseline (speedup 1.0000x reference)
#include <cuda_runtime.h>
#include <math.h>

#define Bn   8
#define Gn   1024
#define Mn   8
#define Nn   2048
#define RBFn 50
#define QCH  13     // 13 float4 chunks of r (52 padded)
#define NPAIR 28    // i<j pairs of 8 particles
#define Hn   128
#define Fn   3200
#define Tn   8      // (b,g) pairs per CTA in main kernel
#define KROW 424    // smv row stride per k: 53*8 floats
#define XC_ROWS 32
#define XC_CHUNK 512
#define LSE_CH  32

// f32x2 packed math helpers
#define FMA2(d, a, b, c) \
    asm("fma.rn.f32x2 %0, %1, %2, %3;" : "=l"(d) : "l"(a), "l"(b), "l"(c))
#define PK2(d, x) \
    asm("mov.b64 %0, {%1, %1};" : "=l"(d) : "f"(x))
#define UNPK2(lo, hi, v) \
    asm("mov.b64 {%0, %1}, %2;" : "=f"(lo), "=f"(hi) : "l"(v))

__constant__ int c_pi[NPAIR] = {0,0,0,0,0,0,0, 1,1,1,1,1,1, 2,2,2,2,2, 3,3,3,3, 4,4,4, 5,5, 6};
__constant__ int c_pj[NPAIR] = {1,2,3,4,5,6,7, 2,3,4,5,6,7, 3,4,5,6,7, 4,5,6,7, 5,6,7, 6,7, 7};

// -------------------- scratch (static device globals) --------------------
__device__ __align__(16) float g_WLp[NPAIR * QCH * Hn * 4];
__device__ __align__(16) float g_WRp[NPAIR * QCH * Hn * 4];
__device__ float g_xc[Bn * Gn * Mn * 3];
__device__ float g_att[Bn * Gn * Hn];
__device__ float g_lsem[Bn * LSE_CH * Hn];
__device__ float g_lses[Bn * LSE_CH * Hn];

// ---------- kernel 1: fold + repack weights ----------
__global__ void __launch_bounds__(128)
pad_weights_kernel(const float* __restrict__ WL, const float* __restrict__ WR) {
    int kq = blockIdx.x;              // 0..363
    int k  = kq / QCH;
    int q  = kq - k * QCH;
    int h  = threadIdx.x;
    int i  = c_pi[k], j = c_pj[k];
    #pragma unroll
    for (int rr = 0; rr < 4; rr++) {
        int r = q * 4 + rr;
        float vL = 0.f, vR = 0.f;
        if (r < RBFn) {
            int fij = (i * Mn + j) * RBFn + r;
            int fji = (j * Mn + i) * RBFn + r;
            vL = WL[h * Fn + fij] - WL[h * Fn + fji];
            vR = WR[h * Fn + fij] - WR[h * Fn + fji];
        }
        int idx = (kq * Hn + h) * 4 + rr;
        g_WLp[idx] = vL;
        g_WRp[idx] = vR;
    }
}

// ---------- kernel 2: xc = batched thin GEMM (f32x2, chunked) ----------
__global__ void __launch_bounds__(XC_ROWS * 12, 2)
xc_kernel(const float* __restrict__ x, const float* __restrict__ Wmap) {
    extern __shared__ float xs[];  // [XC_CHUNK][24] = 49152 B

    int row = blockIdx.x * XC_ROWS + threadIdx.x / 12;
    int c2  = threadIdx.x % 12;

    const float4* __restrict__ wrow =
        reinterpret_cast<const float4*>(Wmap) + (size_t)row * (Nn / 4);

    unsigned long long a0 = 0ull, a1 = 0ull, a2 = 0ull, a3 = 0ull;

    for (int ch = 0; ch < Nn / XC_CHUNK; ch++) {
        __syncthreads();
        for (int e = threadIdx.x; e < Bn * XC_CHUNK * 3; e += XC_ROWS * 12) {
            int b   = e / (XC_CHUNK * 3);
            int rem = e - b * (XC_CHUNK * 3);
            int n   = rem / 3;
            int d   = rem - n * 3;
            xs[n * 24 + b * 3 + d] = x[(b * Nn + ch * XC_CHUNK + n) * 3 + d];
        }
        __syncthreads();

        const float4* wch = wrow + ch * (XC_CHUNK / 4);
        #pragma unroll 8
        for (int n4 = 0; n4 < XC_CHUNK / 4; n4++) {
            float4 w = __ldg(wch + n4);
            const float* xp = xs + n4 * 96 + c2 * 2;
            unsigned long long s0 = *(const unsigned long long*)(xp);
            unsigned long long s1 = *(const unsigned long long*)(xp + 24);
            unsigned long long s2 = *(const unsigned long long*)(xp + 48);
            unsigned long long s3 = *(const unsigned long long*)(xp + 72);
            unsigned long long w0, w1, w2, w3;
            PK2(w0, w.x); PK2(w1, w.y); PK2(w2, w.z); PK2(w3, w.w);
            FMA2(a0, w0, s0, a0);
            FMA2(a1, w1, s1, a1);
            FMA2(a2, w2, s2, a2);
            FMA2(a3, w3, s3, a3);
        }
    }

    float a0lo, a0hi, a1lo, a1hi, a2lo, a2hi, a3lo, a3hi;
    UNPK2(a0lo, a0hi, a0);
    UNPK2(a1lo, a1hi, a1);
    UNPK2(a2lo, a2hi, a2);
    UNPK2(a3lo, a3hi, a3);
    float accA = (a0lo + a1lo) + (a2lo + a3lo);
    float accB = (a0hi + a1hi) + (a2hi + a3hi);

    int cA = c2 * 2;
    int bA = cA / 3, dA = cA - bA * 3;
    g_xc[((size_t)bA * (Gn * Mn) + row) * 3 + dA] = accA;
    int cB = cA + 1;
    int bB = cB / 3, dB = cB - bB * 3;
    g_xc[((size_t)bB * (Gn * Mn) + row) * 3 + dB] = accB;
}

// -------------------- kernel 3: main fused kernel ----------
// Tn=8; 256 threads = h(128) x lr(2); 3 CTAs/SM (6 warps/SMSP).
// Each thread: ONE side (L or R), ALL 28 pairs, 8 t f32x2-packed.
// acc 24 regs + ws 8 regs -> fits the 85-reg cap of (256,3) without spill.
__global__ void __launch_bounds__(256, 3)
main_kernel(float MU0f, float DMf, float INVDMf, float BETAf,
            float TBDf, float BDM2f, float D2f) {
    extern __shared__ float sh[];
    float* smv = sh;                          // 28*424 = 11872 floats
    float* dl  = sh + NPAIR * KROW;           // 28*24  = 672
    float* xcs = dl + NPAIR * 24;             // 192   (50944 B total)

    int bg0 = blockIdx.x * Tn;

    for (int e = threadIdx.x; e < Tn * 24; e += blockDim.x)
        xcs[e] = g_xc[bg0 * 24 + e];
    __syncthreads();

    // ---- Phase A: thread = (k, t); geometric recurrence from peak ----
    if (threadIdx.x < Tn * NPAIR) {
        int k = threadIdx.x >> 3;
        int t = threadIdx.x & 7;
        int i = c_pi[k], j = c_pj[k];
        const float* xt = xcs + t * 24;
        float dx = xt[j * 3 + 0] - xt[i * 3 + 0];
        float dy = xt[j * 3 + 1] - xt[i * 3 + 1];
        float dz = xt[j * 3 + 2] - xt[i * 3 + 2];
        float* drow = dl + k * 24 + t;
        drow[0]  = dx;
        drow[8]  = dy;
        drow[16] = dz;

        float dn  = sqrtf(fmaf(dx, dx, fmaf(dy, dy, dz * dz)) + 1e-5f);
        float uu  = __expf(-dn);
        float cut = (dn < 5.0f)
                  ? 0.5f * (__cosf(dn * 0.6283185307179586f) + 1.0f)
                  : 0.0f;
        float dd   = dn + 1e-5f;
        float coef = cut / (dd * dd);

        float up = uu - MU0f;
        int rs = (int)rintf(up * INVDMf);
        rs = rs < 0 ? 0 : (rs > 49 ? 49 : rs);
        float du = up - (float)rs * DMf;
        float t0 = coef * __expf(-BETAf * du * du);
        float s  = TBDf * up - BDM2f * (float)(2 * rs + 1);
        float qu = __expf(s);
        float qd = __expf(-s) * D2f;

        float* srow = smv + k * KROW + t;
        srow[rs * 8] = t0;
        float tv = t0;
        for (int r = rs + 1; r < RBFn; r++) {
            tv *= qu; qu *= D2f;
            srow[r * 8] = tv;
        }
        tv = t0;
        for (int r = rs - 1; r >= 0; r--) {
            tv *= qd; qd *= D2f;
            srow[r * 8] = tv;
        }
        srow[50 * 8] = 0.f;
        srow[51 * 8] = 0.f;
    }
    __syncthreads();

    // ---- Phase B: one side per thread, all 28 pairs, 8 t packed ----
    int h  = threadIdx.x & 127;
    int lr = threadIdx.x >> 7;

    const float4* __restrict__ w =
        (lr ? (const float4*)g_WRp : (const float4*)g_WLp) + h;

    unsigned long long acc2[4][3] = {{0ull}};

    #pragma unroll 2
    for (int k = 0; k < NPAIR; k++) {
        unsigned long long ws2[4] = {0ull, 0ull, 0ull, 0ull};
        const float* sk = smv + k * KROW;

        #pragma unroll
        for (int q = 0; q < QCH; q++) {
            float4 a = __ldg(w + (size_t)(k * QCH + q) * Hn);

            #define DO_RR(RR, AV)                                              \
            {                                                                  \
                const ulonglong2* sp =                                         \
                    (const ulonglong2*)(sk + (q * 4 + (RR)) * 8);              \
                ulonglong2 s01 = sp[0];                                        \
                ulonglong2 s23 = sp[1];                                        \
                unsigned long long a2;                                         \
                PK2(a2, (AV));                                                 \
                FMA2(ws2[0], a2, s01.x, ws2[0]);                               \
                FMA2(ws2[1], a2, s01.y, ws2[1]);                               \
                FMA2(ws2[2], a2, s23.x, ws2[2]);                               \
                FMA2(ws2[3], a2, s23.y, ws2[3]);                               \
            }
            DO_RR(0, a.x)
            DO_RR(1, a.y)
            DO_RR(2, a.z)
            DO_RR(3, a.w)
            #undef DO_RR
        }

        const ulonglong2* dp = ((const ulonglong2*)(dl + k * 24));
        #pragma unroll
        for (int d = 0; d < 3; d++) {
            ulonglong2 d01 = dp[d * 2 + 0];
            ulonglong2 d23 = dp[d * 2 + 1];
            FMA2(acc2[0][d], ws2[0], d01.x, acc2[0][d]);
            FMA2(acc2[1][d], ws2[1], d01.y, acc2[1][d]);
            FMA2(acc2[2][d], ws2[2], d23.x, acc2[2][d]);
            FMA2(acc2[3][d], ws2[3], d23.y, acc2[3][d]);
        }
    }

    // ---- combine L (lr=0) x R (lr=1) via padded smem (stride 25) ----
    __syncthreads();
    float* red = sh;   // 128*25 = 3200 floats <= 11872
    if (lr == 1) {
        float* r0 = red + h * 25;
        #pragma unroll
        for (int u = 0; u < 4; u++) {
            #pragma unroll
            for (int d = 0; d < 3; d++) {
                float lo, hi;
                UNPK2(lo, hi, acc2[u][d]);
                r0[(2 * u) * 3 + d]     = lo;
                r0[(2 * u + 1) * 3 + d] = hi;
            }
        }
    }
    __syncthreads();
    if (lr == 0) {
        const float* r0 = red + h * 25;
        #pragma unroll
        for (int u = 0; u < 4; u++) {
            float L[2][3];
            #pragma unroll
            for (int d = 0; d < 3; d++)
                UNPK2(L[0][d], L[1][d], acc2[u][d]);
            #pragma unroll
            for (int e = 0; e < 2; e++) {
                int tt = 2 * u + e;
                float att = fmaf(L[e][0], r0[tt * 3 + 0],
                            fmaf(L[e][1], r0[tt * 3 + 1],
                                 L[e][2] * r0[tt * 3 + 2])) + 1e-5f;
                g_att[(size_t)(bg0 + tt) * Hn + h] = att;
            }
        }
    }
}

// ---------- kernel 4a: partial logsumexp ----------
__global__ void __launch_bounds__(128)
lse_partial_kernel() {
    int b  = blockIdx.y;
    int ch = blockIdx.x;
    int h  = threadIdx.x;
    const int GPC = Gn / LSE_CH;
    const float* base = g_att + ((size_t)b * Gn + ch * GPC) * Hn + h;

    float v[GPC];
    #pragma unroll
    for (int i = 0; i < GPC; i++) v[i] = base[(size_t)i * Hn];

    float mx = v[0];
    #pragma unroll
    for (int i = 1; i < GPC; i++) mx = fmaxf(mx, v[i]);
    float s = 0.f;
    #pragma unroll
    for (int i = 0; i < GPC; i++) s += __expf(v[i] - mx);

    g_lsem[(b * LSE_CH + ch) * Hn + h] = mx;
    g_lses[(b * LSE_CH + ch) * Hn + h] = s;
}

// ---------- kernel 4b: combine + MLP ----------
__global__ void __launch_bounds__(128)
finalize_kernel(const float* __restrict__ fc1w, const float* __restrict__ fc1b,
                const float* __restrict__ fc2w, const float* __restrict__ fc2b,
                float* __restrict__ out) {
    int b = blockIdx.x;
    int h = threadIdx.x;

    float M = -3.4e38f;
    #pragma unroll
    for (int ch = 0; ch < LSE_CH; ch++)
        M = fmaxf(M, g_lsem[(b * LSE_CH + ch) * Hn + h]);
    float S = 0.f;
    #pragma unroll
    for (int ch = 0; ch < LSE_CH; ch++) {
        float m = g_lsem[(b * LSE_CH + ch) * Hn + h];
        float s = g_lses[(b * LSE_CH + ch) * Hn + h];
        S += s * __expf(m - M);
    }
    float pooled = M + logf(S);

    __shared__ float ps[Hn];
    __shared__ float red[Hn];
    ps[h] = pooled;
    __syncthreads();

    float a = fc1b[h];
    #pragma unroll 8
    for (int i = 0; i < Hn; i++) a = fmaf(fc1w[h * Hn + i], ps[i], a);
    float hv = a / (1.f + __expf(-a));

    red[h] = hv * fc2w[h];
    __syncthreads();
    for (int st = 64; st > 0; st >>= 1) {
        if (h < st) red[h] += red[h + st];
        __syncthreads();
    }
    if (h == 0) out[b] = red[0] + fc2b[0];
}

// -------------------- launcher --------------------
extern "C" void kernel_launch(void* const* d_in, const int* in_sizes, int n_in,
                              void* d_out, int out_size) {
    const float* x    = (const float*)d_in[0];
    const float* Wmap = (const float*)d_in[1];
    const float* WL   = (const float*)d_in[2];
    const float* WR   = (const float*)d_in[3];
    const float* fc1w = (const float*)d_in[4];
    const float* fc1b = (const float*)d_in[5];
    const float* fc2w = (const float*)d_in[6];
    const float* fc2b = (const float*)d_in[7];
    float* out = (float*)d_out;

    double mu0  = exp(-5.0);
    double dm   = (1.0 - mu0) / 49.0;
    double beta = pow(2.0 / 50.0 * (1.0 - mu0), -2.0);
    double tbd  = 2.0 * beta * dm;
    double bdm2 = beta * dm * dm;
    double d2   = exp(-2.0 * bdm2);

    const int smem_xc   = XC_CHUNK * 24 * (int)sizeof(float);   // 49152
    const int smem_main = (NPAIR * KROW + NPAIR * 24 + Tn * 24) * (int)sizeof(float);

    cudaFuncSetAttribute(xc_kernel, cudaFuncAttributeMaxDynamicSharedMemorySize, smem_xc);
    cudaFuncSetAttribute(main_kernel, cudaFuncAttributeMaxDynamicSharedMemorySize, smem_main);

    pad_weights_kernel<<<NPAIR * QCH, 128>>>(WL, WR);
    xc_kernel<<<(Gn * Mn) / XC_ROWS, XC_ROWS * 12, smem_xc>>>(x, Wmap);
    main_kernel<<<(Bn * Gn) / Tn, 256, smem_main>>>(
        (float)mu0, (float)dm, (float)(1.0 / dm), (float)beta,
        (float)tbd, (float)bdm2, (float)d2);
    lse_partial_kernel<<<dim3(LSE_CH, Bn), 128>>>();
    finalize_kernel<<<Bn, 128>>>(fc1w, fc1b, fc2w, fc2b, out);
}

// round 12
// speedup vs baseline: 1.3786x; 1.3786x over previous
#include <cuda_runtime.h>
#include <cuda_bf16.h>
#include <math.h>

#define Bn   8
#define Gn   1024
#define Mn   8
#define Nn   2048
#define RBFn 50
#define QCH  13     // 13 chunks of 4 r (52 padded)
#define NPAIR 28    // i<j pairs of 8 particles
#define Hn   128
#define Fn   3200
#define Tn   8      // (b,g) pairs per CTA in main kernel
#define KROW 424    // smv row stride per k: 53*8 floats
#define XC_ROWS 32
#define XC_CHUNK 512
#define LSE_CH  32

// f32x2 packed math helpers
#define FMA2(d, a, b, c) \
    asm("fma.rn.f32x2 %0, %1, %2, %3;" : "=l"(d) : "l"(a), "l"(b), "l"(c))
#define PK2(d, x) \
    asm("mov.b64 %0, {%1, %1};" : "=l"(d) : "f"(x))
#define UNPK2(lo, hi, v) \
    asm("mov.b64 {%0, %1}, %2;" : "=f"(lo), "=f"(hi) : "l"(v))

// bf16 (packed in u32) -> f32: low half is a shift, high half a mask
#define BFLO(u) __uint_as_float((u) << 16)
#define BFHI(u) __uint_as_float((u) & 0xFFFF0000u)

__constant__ int c_pi[NPAIR] = {0,0,0,0,0,0,0, 1,1,1,1,1,1, 2,2,2,2,2, 3,3,3,3, 4,4,4, 5,5, 6};
__constant__ int c_pj[NPAIR] = {1,2,3,4,5,6,7, 2,3,4,5,6,7, 3,4,5,6,7, 4,5,6,7, 5,6,7, 6,7, 7};

// -------------------- scratch (static device globals) --------------------
// bf16 folded weights, L/R interleaved: [kq(364)][h(128)] as uint4
// uint4.x = L(r0)|L(r1)<<16, .y = L(r2)|L(r3)<<16, .z/.w = same for R
__device__ __align__(16) uint4 g_Wbf[NPAIR * QCH * Hn];
__device__ float g_xc[Bn * Gn * Mn * 3];
__device__ float g_att[Bn * Gn * Hn];
__device__ float g_lsem[Bn * LSE_CH * Hn];
__device__ float g_lses[Bn * LSE_CH * Hn];

// ---------- kernel 1: fold + repack weights to interleaved bf16 ----------
__global__ void __launch_bounds__(128)
pad_weights_kernel(const float* __restrict__ WL, const float* __restrict__ WR) {
    int kq = blockIdx.x;              // 0..363
    int k  = kq / QCH;
    int q  = kq - k * QCH;
    int h  = threadIdx.x;
    int i  = c_pi[k], j = c_pj[k];
    float vL[4], vR[4];
    #pragma unroll
    for (int rr = 0; rr < 4; rr++) {
        int r = q * 4 + rr;
        vL[rr] = 0.f; vR[rr] = 0.f;
        if (r < RBFn) {
            int fij = (i * Mn + j) * RBFn + r;
            int fji = (j * Mn + i) * RBFn + r;
            vL[rr] = WL[h * Fn + fij] - WL[h * Fn + fji];
            vR[rr] = WR[h * Fn + fij] - WR[h * Fn + fji];
        }
    }
    __nv_bfloat162 lx = __floats2bfloat162_rn(vL[0], vL[1]);
    __nv_bfloat162 ly = __floats2bfloat162_rn(vL[2], vL[3]);
    __nv_bfloat162 rx = __floats2bfloat162_rn(vR[0], vR[1]);
    __nv_bfloat162 ry = __floats2bfloat162_rn(vR[2], vR[3]);
    uint4 o;
    o.x = *(unsigned int*)&lx;
    o.y = *(unsigned int*)&ly;
    o.z = *(unsigned int*)&rx;
    o.w = *(unsigned int*)&ry;
    g_Wbf[kq * Hn + h] = o;
}

// ---------- kernel 2: xc = batched thin GEMM (f32x2, chunked) ----------
__global__ void __launch_bounds__(XC_ROWS * 12, 2)
xc_kernel(const float* __restrict__ x, const float* __restrict__ Wmap) {
    extern __shared__ float xs[];  // [XC_CHUNK][24] = 49152 B

    int row = blockIdx.x * XC_ROWS + threadIdx.x / 12;
    int c2  = threadIdx.x % 12;

    const float4* __restrict__ wrow =
        reinterpret_cast<const float4*>(Wmap) + (size_t)row * (Nn / 4);

    unsigned long long a0 = 0ull, a1 = 0ull, a2 = 0ull, a3 = 0ull;

    for (int ch = 0; ch < Nn / XC_CHUNK; ch++) {
        __syncthreads();
        for (int e = threadIdx.x; e < Bn * XC_CHUNK * 3; e += XC_ROWS * 12) {
            int b   = e / (XC_CHUNK * 3);
            int rem = e - b * (XC_CHUNK * 3);
            int n   = rem / 3;
            int d   = rem - n * 3;
            xs[n * 24 + b * 3 + d] = x[(b * Nn + ch * XC_CHUNK + n) * 3 + d];
        }
        __syncthreads();

        const float4* wch = wrow + ch * (XC_CHUNK / 4);
        #pragma unroll 8
        for (int n4 = 0; n4 < XC_CHUNK / 4; n4++) {
            float4 w = __ldg(wch + n4);
            const float* xp = xs + n4 * 96 + c2 * 2;
            unsigned long long s0 = *(const unsigned long long*)(xp);
            unsigned long long s1 = *(const unsigned long long*)(xp + 24);
            unsigned long long s2 = *(const unsigned long long*)(xp + 48);
            unsigned long long s3 = *(const unsigned long long*)(xp + 72);
            unsigned long long w0, w1, w2, w3;
            PK2(w0, w.x); PK2(w1, w.y); PK2(w2, w.z); PK2(w3, w.w);
            FMA2(a0, w0, s0, a0);
            FMA2(a1, w1, s1, a1);
            FMA2(a2, w2, s2, a2);
            FMA2(a3, w3, s3, a3);
        }
    }

    float a0lo, a0hi, a1lo, a1hi, a2lo, a2hi, a3lo, a3hi;
    UNPK2(a0lo, a0hi, a0);
    UNPK2(a1lo, a1hi, a1);
    UNPK2(a2lo, a2hi, a2);
    UNPK2(a3lo, a3hi, a3);
    float accA = (a0lo + a1lo) + (a2lo + a3lo);
    float accB = (a0hi + a1hi) + (a2hi + a3hi);

    int cA = c2 * 2;
    int bA = cA / 3, dA = cA - bA * 3;
    g_xc[((size_t)bA * (Gn * Mn) + row) * 3 + dA] = accA;
    int cB = cA + 1;
    int bB = cB / 3, dB = cB - bB * 3;
    g_xc[((size_t)bB * (Gn * Mn) + row) * 3 + dB] = accB;
}

// -------------------- kernel 3: main fused kernel (R10 shape, bf16 W) -----
// Tn=8, 256 threads = h(128) x pair-half(2), 2 CTA/SM, combined L/R.
__global__ void __launch_bounds__(256, 2)
main_kernel(float MU0f, float DMf, float INVDMf, float BETAf,
            float TBDf, float BDM2f, float D2f) {
    extern __shared__ float sh[];
    float* smv = sh;                          // 28*424 = 11872 floats
    float* dl  = sh + NPAIR * KROW;           // 28*24  = 672
    float* xcs = dl + NPAIR * 24;             // 192

    int bg0 = blockIdx.x * Tn;

    for (int e = threadIdx.x; e < Tn * 24; e += blockDim.x)
        xcs[e] = g_xc[bg0 * 24 + e];
    __syncthreads();

    // ---- Phase A: thread = (k, t); geometric recurrence from peak ----
    if (threadIdx.x < Tn * NPAIR) {
        int k = threadIdx.x >> 3;
        int t = threadIdx.x & 7;
        int i = c_pi[k], j = c_pj[k];
        const float* xt = xcs + t * 24;
        float dx = xt[j * 3 + 0] - xt[i * 3 + 0];
        float dy = xt[j * 3 + 1] - xt[i * 3 + 1];
        float dz = xt[j * 3 + 2] - xt[i * 3 + 2];
        float* drow = dl + k * 24 + t;
        drow[0]  = dx;
        drow[8]  = dy;
        drow[16] = dz;

        float dn  = sqrtf(fmaf(dx, dx, fmaf(dy, dy, dz * dz)) + 1e-5f);
        float uu  = __expf(-dn);
        float cut = (dn < 5.0f)
                  ? 0.5f * (__cosf(dn * 0.6283185307179586f) + 1.0f)
                  : 0.0f;
        float dd   = dn + 1e-5f;
        float coef = cut / (dd * dd);

        float up = uu - MU0f;
        int rs = (int)rintf(up * INVDMf);
        rs = rs < 0 ? 0 : (rs > 49 ? 49 : rs);
        float du = up - (float)rs * DMf;
        float t0 = coef * __expf(-BETAf * du * du);
        float s  = TBDf * up - BDM2f * (float)(2 * rs + 1);
        float qu = __expf(s);
        float qd = __expf(-s) * D2f;

        float* srow = smv + k * KROW + t;
        srow[rs * 8] = t0;
        float tv = t0;
        for (int r = rs + 1; r < RBFn; r++) {
            tv *= qu; qu *= D2f;
            srow[r * 8] = tv;
        }
        tv = t0;
        for (int r = rs - 1; r >= 0; r--) {
            tv *= qd; qd *= D2f;
            srow[r * 8] = tv;
        }
        srow[50 * 8] = 0.f;
        srow[51 * 8] = 0.f;
    }
    __syncthreads();

    // ---- Phase B: combined L/R, bf16 weights (1 LDG per k,q) ----
    int h  = threadIdx.x & 127;
    int ph = threadIdx.x >> 7;

    const uint4* __restrict__ wb = g_Wbf + h;

    unsigned long long acc2L[4][3] = {{0ull}}, acc2R[4][3] = {{0ull}};

    int k0 = ph * (NPAIR / 2);
    #pragma unroll 2
    for (int k = k0; k < k0 + NPAIR / 2; k++) {
        unsigned long long ws2L[4] = {0ull, 0ull, 0ull, 0ull};
        unsigned long long ws2R[4] = {0ull, 0ull, 0ull, 0ull};
        const float* sk = smv + k * KROW;

        #pragma unroll
        for (int q = 0; q < QCH; q++) {
            uint4 wp = __ldg(wb + (size_t)(k * QCH + q) * Hn);

            #define DO_RR(RR, AV, CV)                                          \
            {                                                                  \
                const ulonglong2* sp =                                         \
                    (const ulonglong2*)(sk + (q * 4 + (RR)) * 8);              \
                ulonglong2 s01 = sp[0];                                        \
                ulonglong2 s23 = sp[1];                                        \
                unsigned long long a2, c2;                                     \
                PK2(a2, (AV)); PK2(c2, (CV));                                  \
                FMA2(ws2L[0], a2, s01.x, ws2L[0]);                             \
                FMA2(ws2L[1], a2, s01.y, ws2L[1]);                             \
                FMA2(ws2L[2], a2, s23.x, ws2L[2]);                             \
                FMA2(ws2L[3], a2, s23.y, ws2L[3]);                             \
                FMA2(ws2R[0], c2, s01.x, ws2R[0]);                             \
                FMA2(ws2R[1], c2, s01.y, ws2R[1]);                             \
                FMA2(ws2R[2], c2, s23.x, ws2R[2]);                             \
                FMA2(ws2R[3], c2, s23.y, ws2R[3]);                             \
            }
            DO_RR(0, BFLO(wp.x), BFLO(wp.z))
            DO_RR(1, BFHI(wp.x), BFHI(wp.z))
            DO_RR(2, BFLO(wp.y), BFLO(wp.w))
            DO_RR(3, BFHI(wp.y), BFHI(wp.w))
            #undef DO_RR
        }

        const ulonglong2* dp = ((const ulonglong2*)(dl + k * 24));
        #pragma unroll
        for (int d = 0; d < 3; d++) {
            ulonglong2 d01 = dp[d * 2 + 0];
            ulonglong2 d23 = dp[d * 2 + 1];
            FMA2(acc2L[0][d], ws2L[0], d01.x, acc2L[0][d]);
            FMA2(acc2L[1][d], ws2L[1], d01.y, acc2L[1][d]);
            FMA2(acc2L[2][d], ws2L[2], d23.x, acc2L[2][d]);
            FMA2(acc2L[3][d], ws2L[3], d23.y, acc2L[3][d]);
            FMA2(acc2R[0][d], ws2R[0], d01.x, acc2R[0][d]);
            FMA2(acc2R[1][d], ws2R[1], d01.y, acc2R[1][d]);
            FMA2(acc2R[2][d], ws2R[2], d23.x, acc2R[2][d]);
            FMA2(acc2R[3][d], ws2R[3], d23.y, acc2R[3][d]);
        }
    }

    // ---- cross-half reduction (reuse smv; stride 49) ----
    __syncthreads();
    float* red = smv;
    if (ph == 1) {
        float* r0 = red + h * 49;
        #pragma unroll
        for (int u = 0; u < 4; u++) {
            #pragma unroll
            for (int d = 0; d < 3; d++) {
                float lo, hi;
                UNPK2(lo, hi, acc2L[u][d]);
                r0[(2 * u) * 6 + d]     = lo;
                r0[(2 * u + 1) * 6 + d] = hi;
                UNPK2(lo, hi, acc2R[u][d]);
                r0[(2 * u) * 6 + 3 + d]     = lo;
                r0[(2 * u + 1) * 6 + 3 + d] = hi;
            }
        }
    }
    __syncthreads();
    if (ph == 0) {
        const float* r0 = red + h * 49;
        #pragma unroll
        for (int u = 0; u < 4; u++) {
            float L[2][3], R[2][3];
            #pragma unroll
            for (int d = 0; d < 3; d++) {
                UNPK2(L[0][d], L[1][d], acc2L[u][d]);
                UNPK2(R[0][d], R[1][d], acc2R[u][d]);
            }
            #pragma unroll
            for (int e = 0; e < 2; e++) {
                int tt = 2 * u + e;
                float L0 = L[e][0] + r0[tt * 6 + 0];
                float L1 = L[e][1] + r0[tt * 6 + 1];
                float L2 = L[e][2] + r0[tt * 6 + 2];
                float R0 = R[e][0] + r0[tt * 6 + 3];
                float R1 = R[e][1] + r0[tt * 6 + 4];
                float R2 = R[e][2] + r0[tt * 6 + 5];
                float att = fmaf(L0, R0, fmaf(L1, R1, L2 * R2)) + 1e-5f;
                g_att[(size_t)(bg0 + tt) * Hn + h] = att;
            }
        }
    }
}

// ---------- kernel 4a: partial logsumexp ----------
__global__ void __launch_bounds__(128)
lse_partial_kernel() {
    int b  = blockIdx.y;
    int ch = blockIdx.x;
    int h  = threadIdx.x;
    const int GPC = Gn / LSE_CH;
    const float* base = g_att + ((size_t)b * Gn + ch * GPC) * Hn + h;

    float v[GPC];
    #pragma unroll
    for (int i = 0; i < GPC; i++) v[i] = base[(size_t)i * Hn];

    float mx = v[0];
    #pragma unroll
    for (int i = 1; i < GPC; i++) mx = fmaxf(mx, v[i]);
    float s = 0.f;
    #pragma unroll
    for (int i = 0; i < GPC; i++) s += __expf(v[i] - mx);

    g_lsem[(b * LSE_CH + ch) * Hn + h] = mx;
    g_lses[(b * LSE_CH + ch) * Hn + h] = s;
}

// ---------- kernel 4b: combine + MLP ----------
__global__ void __launch_bounds__(128)
finalize_kernel(const float* __restrict__ fc1w, const float* __restrict__ fc1b,
                const float* __restrict__ fc2w, const float* __restrict__ fc2b,
                float* __restrict__ out) {
    int b = blockIdx.x;
    int h = threadIdx.x;

    float M = -3.4e38f;
    #pragma unroll
    for (int ch = 0; ch < LSE_CH; ch++)
        M = fmaxf(M, g_lsem[(b * LSE_CH + ch) * Hn + h]);
    float S = 0.f;
    #pragma unroll
    for (int ch = 0; ch < LSE_CH; ch++) {
        float m = g_lsem[(b * LSE_CH + ch) * Hn + h];
        float s = g_lses[(b * LSE_CH + ch) * Hn + h];
        S += s * __expf(m - M);
    }
    float pooled = M + logf(S);

    __shared__ float ps[Hn];
    __shared__ float red[Hn];
    ps[h] = pooled;
    __syncthreads();

    float a = fc1b[h];
    #pragma unroll 8
    for (int i = 0; i < Hn; i++) a = fmaf(fc1w[h * Hn + i], ps[i], a);
    float hv = a / (1.f + __expf(-a));

    red[h] = hv * fc2w[h];
    __syncthreads();
    for (int st = 64; st > 0; st >>= 1) {
        if (h < st) red[h] += red[h + st];
        __syncthreads();
    }
    if (h == 0) out[b] = red[0] + fc2b[0];
}

// -------------------- launcher --------------------
extern "C" void kernel_launch(void* const* d_in, const int* in_sizes, int n_in,
                              void* d_out, int out_size) {
    const float* x    = (const float*)d_in[0];
    const float* Wmap = (const float*)d_in[1];
    const float* WL   = (const float*)d_in[2];
    const float* WR   = (const float*)d_in[3];
    const float* fc1w = (const float*)d_in[4];
    const float* fc1b = (const float*)d_in[5];
    const float* fc2w = (const float*)d_in[6];
    const float* fc2b = (const float*)d_in[7];
    float* out = (float*)d_out;

    double mu0  = exp(-5.0);
    double dm   = (1.0 - mu0) / 49.0;
    double beta = pow(2.0 / 50.0 * (1.0 - mu0), -2.0);
    double tbd  = 2.0 * beta * dm;
    double bdm2 = beta * dm * dm;
    double d2   = exp(-2.0 * bdm2);

    const int smem_xc   = XC_CHUNK * 24 * (int)sizeof(float);   // 49152
    const int smem_main = (NPAIR * KROW + NPAIR * 24 + Tn * 24) * (int)sizeof(float);

    cudaFuncSetAttribute(xc_kernel, cudaFuncAttributeMaxDynamicSharedMemorySize, smem_xc);
    cudaFuncSetAttribute(main_kernel, cudaFuncAttributeMaxDynamicSharedMemorySize, smem_main);

    pad_weights_kernel<<<NPAIR * QCH, 128>>>(WL, WR);
    xc_kernel<<<(Gn * Mn) / XC_ROWS, XC_ROWS * 12, smem_xc>>>(x, Wmap);
    main_kernel<<<(Bn * Gn) / Tn, 256, smem_main>>>(
        (float)mu0, (float)dm, (float)(1.0 / dm), (float)beta,
        (float)tbd, (float)bdm2, (float)d2);
    lse_partial_kernel<<<dim3(LSE_CH, Bn), 128>>>();
    finalize_kernel<<<Bn, 128>>>(fc1w, fc1b, fc2w, fc2b, out);
}